// round 2
// baseline (speedup 1.0000x reference)
#include <cuda_runtime.h>
#include <math.h>

#define EPSF 1e-05f
#define NB 1024
#define BB 8
#define DD 128
#define PP 16
#define KA (PP*DD)   /* 2048 */

// ---------------- scratch (static device globals; no allocation) ----------------
__device__ float g_A  [(size_t)BB*NB*KA];   // 64 MiB  normalized/scaled context features
__device__ float g_S  [(size_t)BB*NB*NB];   // 32 MiB  selfwind (row-normalized)
__device__ float g_ATT[(size_t)BB*NB*NB];   // 32 MiB  relu(attention)
__device__ float g_Y  [(size_t)BB*NB*NB];   // 32 MiB  gamma*SS^T/20 + EPS
__device__ float g_cosA[(size_t)NB*NB];     // 4 MiB
__device__ float g_sinA[(size_t)NB*NB];     // 4 MiB
__device__ float g_cu[BB*NB], g_su[BB*NB], g_ta[BB*NB], g_aspd[BB*NB];

// ---------------- helpers ----------------
__device__ __forceinline__ float blockReduce256(float v) {
    __shared__ float sh[8];
    int lane = threadIdx.x & 31, w = threadIdx.x >> 5;
    #pragma unroll
    for (int o = 16; o; o >>= 1) v += __shfl_xor_sync(0xffffffffu, v, o);
    if (lane == 0) sh[w] = v;
    __syncthreads();
    float t = 0.f;
    #pragma unroll
    for (int i = 0; i < 8; i++) t += sh[i];
    __syncthreads();
    return t;
}

// ---------------- small prep: per (b,n) scalars ----------------
__global__ void prep_small_k(const float* __restrict__ acc_u, const float* __restrict__ acc_v,
                             const float* __restrict__ uv,    const float* __restrict__ uva,
                             const float* __restrict__ speed) {
    int i = blockIdx.x * 256 + threadIdx.x;
    if (i >= BB * NB) return;
    float au = acc_u[i], av = acc_v[i];
    float x1 = sqrtf(au * au + av * av + EPSF);
    float x2 = fabsf(cosf(uva[i] - uv[i]));
    g_ta[i]   = x1 * x2;
    float s, c;
    sincosf(uv[i], &s, &c);
    g_cu[i]   = c;
    g_su[i]   = s;
    g_aspd[i] = fabsf(speed[i]);
}

// ---------------- sincos of angle (N x N) ----------------
__global__ void angle_k(const float* __restrict__ angle) {
    int i = blockIdx.x * 256 + threadIdx.x;
    if (i >= NB * NB) return;
    float s, c;
    sincosf(angle[i], &s, &c);
    g_cosA[i] = c;
    g_sinA[i] = s;
}

// ---------------- build A: one block per (b,n), 128 threads (d) ----------------
__global__ void buildA_k(const float* __restrict__ context, const float* __restrict__ weight) {
    int bn = blockIdx.x;
    int d  = threadIdx.x;
    float c = context[(size_t)bn * DD + d];
    __shared__ float red[PP][4];
    float vp[PP];
    int lane = d & 31, w = d >> 5;
    #pragma unroll
    for (int p = 0; p < PP; p++) {
        float v = c * weight[p * DD + d];
        vp[p] = v;
        float s = v * v;
        #pragma unroll
        for (int o = 16; o; o >>= 1) s += __shfl_xor_sync(0xffffffffu, s, o);
        if (lane == 0) red[p][w] = s;
    }
    __syncthreads();
    const float invsqrtP = 0.25f;  // 1/sqrt(16): folds the /P of attention into A·A^T
    size_t base = (size_t)bn * KA + d;
    #pragma unroll
    for (int p = 0; p < PP; p++) {
        float tot = red[p][0] + red[p][1] + red[p][2] + red[p][3];
        float inv = invsqrtP / fmaxf(sqrtf(tot), 1e-12f);
        g_A[base + p * DD] = vp[p] * inv;
    }
}

// ---------------- selfwind: one block per (b,n), 256 threads ----------------
__global__ void selfwind_k(const float* __restrict__ dist) {
    int bn = blockIdx.x;
    int n  = bn & (NB - 1);
    float cu = g_cu[bn], su = g_su[bn], ta = g_ta[bn], spd = g_aspd[bn];
    float vr[4];
    float ss = 0.f;
    #pragma unroll
    for (int i = 0; i < 4; i++) {
        int k = threadIdx.x + i * 256;
        float cv = g_cosA[(size_t)n * NB + k] * cu + g_sinA[(size_t)n * NB + k] * su;
        if (k == n) cv += 0.5f * ta;                 // sigma * temp_acc on diagonal
        float v = spd * fabsf(cv) / (dist[(size_t)n * NB + k] + EPSF);
        vr[i] = v;
        ss += v * v;
    }
    float tot = blockReduce256(ss);
    float inv = 1.0f / fmaxf(sqrtf(tot), 1e-12f);
    size_t base = (size_t)bn * NB;
    #pragma unroll
    for (int i = 0; i < 4; i++) g_S[base + threadIdx.x + i * 256] = vr[i] * inv;
}

// ---------------- batched SYRK, triangular tiles, 128x128x8 smem-tiled ----------------
// which==0: dst = relu(A A^T)      (src g_A,  K=2048, dst g_ATT)
// which==1: dst = 0.07*(S S^T)+EPS (src g_S,  K=1024, dst g_Y)
__global__ void __launch_bounds__(256, 2) syrk_k(int which) {
    const float* __restrict__ src = which ? g_S : g_A;
    float* __restrict__ dst = which ? g_Y : g_ATT;
    const int K = which ? NB : KA;

    int b   = blockIdx.y;
    int lin = blockIdx.x;
    int bi = 0;
    while ((bi + 1) * (bi + 2) / 2 <= lin) bi++;
    int bj = lin - bi * (bi + 1) / 2;

    __shared__ float As[8][132];
    __shared__ float Bs[8][132];

    int tid = threadIdx.x;
    int tx = tid & 15, ty = tid >> 4;
    int loadRow = tid >> 1;
    int loadCol = (tid & 1) * 4;

    const float* Ap = src + ((size_t)b * NB + bi * 128 + loadRow) * K + loadCol;
    const float* Bp = src + ((size_t)b * NB + bj * 128 + loadRow) * K + loadCol;

    float acc[8][8];
    #pragma unroll
    for (int i = 0; i < 8; i++)
        #pragma unroll
        for (int j = 0; j < 8; j++) acc[i][j] = 0.f;

    for (int k0 = 0; k0 < K; k0 += 8) {
        float4 av = *(const float4*)(Ap + k0);
        float4 bv = *(const float4*)(Bp + k0);
        __syncthreads();
        As[loadCol + 0][loadRow] = av.x;
        As[loadCol + 1][loadRow] = av.y;
        As[loadCol + 2][loadRow] = av.z;
        As[loadCol + 3][loadRow] = av.w;
        Bs[loadCol + 0][loadRow] = bv.x;
        Bs[loadCol + 1][loadRow] = bv.y;
        Bs[loadCol + 2][loadRow] = bv.z;
        Bs[loadCol + 3][loadRow] = bv.w;
        __syncthreads();
        #pragma unroll
        for (int kk = 0; kk < 8; kk++) {
            float4 a0 = *(const float4*)&As[kk][ty * 4];
            float4 a1 = *(const float4*)&As[kk][64 + ty * 4];
            float4 b0 = *(const float4*)&Bs[kk][tx * 4];
            float4 b1 = *(const float4*)&Bs[kk][64 + tx * 4];
            float ar[8] = {a0.x, a0.y, a0.z, a0.w, a1.x, a1.y, a1.z, a1.w};
            float br[8] = {b0.x, b0.y, b0.z, b0.w, b1.x, b1.y, b1.z, b1.w};
            #pragma unroll
            for (int i = 0; i < 8; i++)
                #pragma unroll
                for (int j = 0; j < 8; j++)
                    acc[i][j] = fmaf(ar[i], br[j], acc[i][j]);
        }
    }

    const float gscale = 1.4f / 20.0f;
    size_t cbase = (size_t)b * NB * NB;
    int row0 = bi * 128, col0 = bj * 128;

    #pragma unroll
    for (int i = 0; i < 8; i++) {
        int r = row0 + ((i < 4) ? ty * 4 + i : 64 + ty * 4 + i - 4);
        float* p = dst + cbase + (size_t)r * NB;
        float v[8];
        #pragma unroll
        for (int j = 0; j < 8; j++)
            v[j] = which ? fmaf(acc[i][j], gscale, EPSF) : fmaxf(acc[i][j], 0.f);
        *(float4*)(p + col0 + tx * 4)      = make_float4(v[0], v[1], v[2], v[3]);
        *(float4*)(p + col0 + 64 + tx * 4) = make_float4(v[4], v[5], v[6], v[7]);
    }
    if (bi != bj) {
        #pragma unroll
        for (int j = 0; j < 8; j++) {
            int r = col0 + ((j < 4) ? tx * 4 + j : 64 + tx * 4 + j - 4);
            float* p = dst + cbase + (size_t)r * NB;
            float v[8];
            #pragma unroll
            for (int i = 0; i < 8; i++)
                v[i] = which ? fmaf(acc[i][j], gscale, EPSF) : fmaxf(acc[i][j], 0.f);
            *(float4*)(p + row0 + ty * 4)      = make_float4(v[0], v[1], v[2], v[3]);
            *(float4*)(p + row0 + 64 + ty * 4) = make_float4(v[4], v[5], v[6], v[7]);
        }
    }
}

// ---------------- final fused epilogue: one block per (b,n) row ----------------
__global__ void final_k(float* __restrict__ out) {
    int bn = blockIdx.x;
    size_t base = (size_t)bn * NB;

    float yv[4];
    float ssy = 0.f;
    #pragma unroll
    for (int i = 0; i < 4; i++) {
        int k = threadIdx.x + i * 256;
        float y = g_Y[base + k];
        yv[i] = y;
        ssy += y * y;
    }
    float toty = blockReduce256(ssy);
    float invny = 1.0f / fmaxf(sqrtf(toty), 1e-12f);

    float tv[4];
    float sst = 0.f;
    #pragma unroll
    for (int i = 0; i < 4; i++) {
        int k = threadIdx.x + i * 256;
        float t = fabsf(0.5f * g_S[base + k] + sqrtf(yv[i] * invny)) + EPSF;
        tv[i] = t;
        sst += t * t;
    }
    float tott = blockReduce256(sst);
    float invnt = 1.0f / fmaxf(sqrtf(tott), 1e-12f);

    #pragma unroll
    for (int i = 0; i < 4; i++) {
        int k = threadIdx.x + i * 256;
        out[base + k] = g_ATT[base + k] * tv[i] * invnt;
    }
}

// ---------------- launch ----------------
extern "C" void kernel_launch(void* const* d_in, const int* in_sizes, int n_in,
                              void* d_out, int out_size) {
    const float* context = (const float*)d_in[0];
    const float* acc_u   = (const float*)d_in[1];
    const float* acc_v   = (const float*)d_in[2];
    const float* uv      = (const float*)d_in[3];
    const float* uva     = (const float*)d_in[4];
    const float* speed   = (const float*)d_in[5];
    /* d_in[6] = isPhy (unused by the reference) */
    const float* dist    = (const float*)d_in[7];
    const float* angle   = (const float*)d_in[8];
    const float* weight  = (const float*)d_in[9];
    float* out = (float*)d_out;

    prep_small_k<<<(BB * NB + 255) / 256, 256>>>(acc_u, acc_v, uv, uva, speed);
    angle_k<<<(NB * NB + 255) / 256, 256>>>(angle);
    buildA_k<<<BB * NB, 128>>>(context, weight);
    selfwind_k<<<BB * NB, 256>>>(dist);

    dim3 gg(36, BB);                 // 8 tiles -> 36 lower-triangular tile pairs
    syrk_k<<<gg, 256>>>(0);          // attention = relu(A A^T)
    syrk_k<<<gg, 256>>>(1);          // y = gamma*(S S^T)/20 + EPS

    final_k<<<BB * NB, 256>>>(out);
}

// round 12
// speedup vs baseline: 1.7255x; 1.7255x over previous
#include <cuda_runtime.h>
#include <cuda_bf16.h>
#include <math.h>
#include <stdint.h>

#define EPSF 1e-05f
#define NB 1024
#define BB 8
#define DD 128
#define PP 16
#define KA (PP*DD)   /* 2048 */

// ---------------- scratch (static device globals; no allocation) ----------------
__device__ __nv_bfloat16 g_Ah[(size_t)BB*NB*KA];  // 32 MiB  hi part of normalized features
__device__ __nv_bfloat16 g_Al[(size_t)BB*NB*KA];  // 32 MiB  lo part
__device__ __nv_bfloat16 g_Sh[(size_t)BB*NB*NB];  // 16 MiB  hi part of selfwind
__device__ __nv_bfloat16 g_Sl[(size_t)BB*NB*NB];  // 16 MiB  lo part
__device__ float g_S  [(size_t)BB*NB*NB];   // 32 MiB  selfwind fp32 (final epilogue)
__device__ float g_ATT[(size_t)BB*NB*NB];   // 32 MiB  relu(attention)
__device__ float g_Y  [(size_t)BB*NB*NB];   // 32 MiB  gamma*SS^T/20 + EPS
__device__ float g_cosA[(size_t)NB*NB];     // 4 MiB
__device__ float g_sinA[(size_t)NB*NB];     // 4 MiB
__device__ float g_cu[BB*NB], g_su[BB*NB], g_ta[BB*NB], g_aspd[BB*NB];

// ---------------- helpers ----------------
__device__ __forceinline__ float blockReduce256(float v) {
    __shared__ float sh[8];
    int lane = threadIdx.x & 31, w = threadIdx.x >> 5;
    #pragma unroll
    for (int o = 16; o; o >>= 1) v += __shfl_xor_sync(0xffffffffu, v, o);
    if (lane == 0) sh[w] = v;
    __syncthreads();
    float t = 0.f;
    #pragma unroll
    for (int i = 0; i < 8; i++) t += sh[i];
    __syncthreads();
    return t;
}
__device__ __forceinline__ void split_bf16(float x, __nv_bfloat16& h, __nv_bfloat16& l) {
    h = __float2bfloat16(x);
    l = __float2bfloat16(x - __bfloat162float(h));
}
// m16n8k16 row.col bf16 MMA with fp32 accumulate (sm_80+ PTX, no 'a' features)
__device__ __forceinline__ void mma16816(float* d, const uint32_t* a, const uint32_t* b) {
    asm volatile(
        "mma.sync.aligned.m16n8k16.row.col.f32.bf16.bf16.f32 "
        "{%0,%1,%2,%3}, {%4,%5,%6,%7}, {%8,%9}, {%0,%1,%2,%3};"
        : "+f"(d[0]), "+f"(d[1]), "+f"(d[2]), "+f"(d[3])
        : "r"(a[0]), "r"(a[1]), "r"(a[2]), "r"(a[3]), "r"(b[0]), "r"(b[1]));
}

// ---------------- small prep: per (b,n) scalars ----------------
__global__ void prep_small_k(const float* __restrict__ acc_u, const float* __restrict__ acc_v,
                             const float* __restrict__ uv,    const float* __restrict__ uva,
                             const float* __restrict__ speed) {
    int i = blockIdx.x * 256 + threadIdx.x;
    if (i >= BB * NB) return;
    float au = acc_u[i], av = acc_v[i];
    float x1 = sqrtf(au * au + av * av + EPSF);
    float x2 = fabsf(cosf(uva[i] - uv[i]));
    g_ta[i]   = x1 * x2;
    float s, c;
    sincosf(uv[i], &s, &c);
    g_cu[i]   = c;
    g_su[i]   = s;
    g_aspd[i] = fabsf(speed[i]);
}

// ---------------- sincos of angle (N x N) ----------------
__global__ void angle_k(const float* __restrict__ angle) {
    int i = blockIdx.x * 256 + threadIdx.x;
    if (i >= NB * NB) return;
    float s, c;
    sincosf(angle[i], &s, &c);
    g_cosA[i] = c;
    g_sinA[i] = s;
}

// ---------------- build A (bf16 hi/lo): one block per (b,n), 128 threads (d) ----------------
__global__ void buildA_k(const float* __restrict__ context, const float* __restrict__ weight) {
    int bn = blockIdx.x;
    int d  = threadIdx.x;
    float c = context[(size_t)bn * DD + d];
    __shared__ float red[PP][4];
    float vp[PP];
    int lane = d & 31, w = d >> 5;
    #pragma unroll
    for (int p = 0; p < PP; p++) {
        float v = c * weight[p * DD + d];
        vp[p] = v;
        float s = v * v;
        #pragma unroll
        for (int o = 16; o; o >>= 1) s += __shfl_xor_sync(0xffffffffu, s, o);
        if (lane == 0) red[p][w] = s;
    }
    __syncthreads();
    const float invsqrtP = 0.25f;  // 1/sqrt(16): folds the /P of attention into A·A^T
    size_t base = (size_t)bn * KA + d;
    #pragma unroll
    for (int p = 0; p < PP; p++) {
        float tot = red[p][0] + red[p][1] + red[p][2] + red[p][3];
        float inv = invsqrtP / fmaxf(sqrtf(tot), 1e-12f);
        float y = vp[p] * inv;
        __nv_bfloat16 h, l;
        split_bf16(y, h, l);
        g_Ah[base + p * DD] = h;
        g_Al[base + p * DD] = l;
    }
}

// ---------------- selfwind: one block per (b,n), 256 threads ----------------
__global__ void selfwind_k(const float* __restrict__ dist) {
    int bn = blockIdx.x;
    int n  = bn & (NB - 1);
    float cu = g_cu[bn], su = g_su[bn], ta = g_ta[bn], spd = g_aspd[bn];
    float vr[4];
    float ss = 0.f;
    #pragma unroll
    for (int i = 0; i < 4; i++) {
        int k = threadIdx.x + i * 256;
        float cv = g_cosA[(size_t)n * NB + k] * cu + g_sinA[(size_t)n * NB + k] * su;
        if (k == n) cv += 0.5f * ta;                 // sigma * temp_acc on diagonal
        float v = spd * fabsf(cv) / (dist[(size_t)n * NB + k] + EPSF);
        vr[i] = v;
        ss += v * v;
    }
    float tot = blockReduce256(ss);
    float inv = 1.0f / fmaxf(sqrtf(tot), 1e-12f);
    size_t base = (size_t)bn * NB;
    #pragma unroll
    for (int i = 0; i < 4; i++) {
        int k = threadIdx.x + i * 256;
        float v = vr[i] * inv;
        g_S[base + k] = v;
        __nv_bfloat16 h, l;
        split_bf16(v, h, l);
        g_Sh[base + k] = h;
        g_Sl[base + k] = l;
    }
}

// ---------------- mma.sync batched SYRK (3-term bf16 split), triangular tiles ----------------
// mode==0: g_ATT = relu(A A^T)        K=2048
// mode==1: g_Y   = 0.07*(S S^T)+EPS   K=1024
// CTA tile 128x128, 8 warps in 2(m) x 4(n), warp tile 64x32, BK=32.
// smem rows padded: 32 bf16 data + 8 pad = 40 bf16 = 20 b32 per row (conflict-free frags).
#define BK 32
#define LDS_STRIDE 20            /* b32 per smem row */
#define TILE_B32 (128*LDS_STRIDE)

__global__ void __launch_bounds__(256, 1) syrk_mma_k(int mode) {
    __shared__ uint32_t sAh[TILE_B32], sAl[TILE_B32], sBh[TILE_B32], sBl[TILE_B32];
    const __nv_bfloat16* __restrict__ hi = mode ? g_Sh : g_Ah;
    const __nv_bfloat16* __restrict__ lo = mode ? g_Sl : g_Al;
    float* __restrict__ dst = mode ? g_Y : g_ATT;
    const int K = mode ? NB : KA;

    const int b = blockIdx.y;
    int lin = blockIdx.x;
    int bi = 0;
    while ((bi + 1) * (bi + 2) / 2 <= lin) bi++;
    int bj = lin - bi * (bi + 1) / 2;
    const int row0 = bi * 128, col0 = bj * 128;

    const int tid = threadIdx.x, wid = tid >> 5, lane = tid & 31;
    const int wm = wid >> 2, wn = wid & 3;      // warp grid 2x4
    const int g = lane >> 2, q = lane & 3;      // fragment row-group / quad

    const size_t baseA = ((size_t)b * NB + row0) * K;
    const size_t baseB = ((size_t)b * NB + col0) * K;

    float acc[4][4][4];
    #pragma unroll
    for (int i = 0; i < 4; i++)
        #pragma unroll
        for (int j = 0; j < 4; j++)
            #pragma unroll
            for (int t = 0; t < 4; t++) acc[i][j][t] = 0.f;

    // global-load bookkeeping: 1024 uint2 per array per chunk, 4 per thread
    int ldrow[4], ldu[4];
    #pragma unroll
    for (int i = 0; i < 4; i++) { int idx = i * 256 + tid; ldrow[i] = idx >> 3; ldu[i] = idx & 7; }

    uint2 pAh[4], pAl[4], pBh[4], pBl[4];

    const int nch = K / BK;
    // prologue load chunk 0
    #pragma unroll
    for (int i = 0; i < 4; i++) {
        size_t oA = baseA + (size_t)ldrow[i] * K + ldu[i] * 4;
        size_t oB = baseB + (size_t)ldrow[i] * K + ldu[i] * 4;
        pAh[i] = *(const uint2*)(hi + oA);  pAl[i] = *(const uint2*)(lo + oA);
        pBh[i] = *(const uint2*)(hi + oB);  pBl[i] = *(const uint2*)(lo + oB);
    }
    #pragma unroll
    for (int i = 0; i < 4; i++) {
        int so = ldrow[i] * LDS_STRIDE + ldu[i] * 2;
        *(uint2*)&sAh[so] = pAh[i];  *(uint2*)&sAl[so] = pAl[i];
        *(uint2*)&sBh[so] = pBh[i];  *(uint2*)&sBl[so] = pBl[i];
    }
    __syncthreads();

    for (int ck = 0; ck < nch; ck++) {
        // prefetch next chunk into registers (overlaps with MMA below)
        if (ck + 1 < nch) {
            const int kb = (ck + 1) * BK;
            #pragma unroll
            for (int i = 0; i < 4; i++) {
                size_t oA = baseA + (size_t)ldrow[i] * K + kb + ldu[i] * 4;
                size_t oB = baseB + (size_t)ldrow[i] * K + kb + ldu[i] * 4;
                pAh[i] = *(const uint2*)(hi + oA);  pAl[i] = *(const uint2*)(lo + oA);
                pBh[i] = *(const uint2*)(hi + oB);  pBl[i] = *(const uint2*)(lo + oB);
            }
        }
        // compute: two k16 steps per chunk
        #pragma unroll
        for (int ks = 0; ks < 2; ks++) {
            const int kb32 = ks * 8;   // 16 bf16 = 8 b32
            uint32_t ah[4][4], al[4][4], bh[4][2], bl[4][2];
            #pragma unroll
            for (int mt = 0; mt < 4; mt++) {
                int r = wm * 64 + mt * 16 + g;
                int a0 = r * LDS_STRIDE + kb32 + q;
                ah[mt][0] = sAh[a0];                      // (g,      k0..k0+1)
                ah[mt][1] = sAh[a0 + 8 * LDS_STRIDE];     // (g+8,    k0..)
                ah[mt][2] = sAh[a0 + 4];                  // (g,      k0+8..)
                ah[mt][3] = sAh[a0 + 8 * LDS_STRIDE + 4]; // (g+8,    k0+8..)
                al[mt][0] = sAl[a0];
                al[mt][1] = sAl[a0 + 8 * LDS_STRIDE];
                al[mt][2] = sAl[a0 + 4];
                al[mt][3] = sAl[a0 + 8 * LDS_STRIDE + 4];
            }
            #pragma unroll
            for (int nt = 0; nt < 4; nt++) {
                int n = wn * 32 + nt * 8 + g;
                int b0 = n * LDS_STRIDE + kb32 + q;
                bh[nt][0] = sBh[b0];        // (k0..k0+1, n)
                bh[nt][1] = sBh[b0 + 4];    // (k0+8..,   n)
                bl[nt][0] = sBl[b0];
                bl[nt][1] = sBl[b0 + 4];
            }
            #pragma unroll
            for (int mt = 0; mt < 4; mt++)
                #pragma unroll
                for (int nt = 0; nt < 4; nt++) {
                    mma16816(acc[mt][nt], ah[mt], bh[nt]);
                    mma16816(acc[mt][nt], ah[mt], bl[nt]);
                    mma16816(acc[mt][nt], al[mt], bh[nt]);
                }
        }
        __syncthreads();
        if (ck + 1 < nch) {
            #pragma unroll
            for (int i = 0; i < 4; i++) {
                int so = ldrow[i] * LDS_STRIDE + ldu[i] * 2;
                *(uint2*)&sAh[so] = pAh[i];  *(uint2*)&sAl[so] = pAl[i];
                *(uint2*)&sBh[so] = pBh[i];  *(uint2*)&sBl[so] = pBl[i];
            }
            __syncthreads();
        }
    }

    // epilogue: pointwise + store (+ mirror for off-diagonal tiles)
    const float gscale = 1.4f / 20.0f;
    const size_t cbase = (size_t)b * NB * NB;
    #pragma unroll
    for (int mt = 0; mt < 4; mt++) {
        #pragma unroll
        for (int nt = 0; nt < 4; nt++) {
            int r = row0 + wm * 64 + mt * 16 + g;
            int c = col0 + wn * 32 + nt * 8 + q * 2;
            float v[4];
            #pragma unroll
            for (int t = 0; t < 4; t++) {
                float f = acc[mt][nt][t];
                v[t] = mode ? fmaf(f, gscale, EPSF) : fmaxf(f, 0.f);
            }
            *(float2*)&dst[cbase + (size_t)r * NB + c]       = make_float2(v[0], v[1]);
            *(float2*)&dst[cbase + (size_t)(r + 8) * NB + c] = make_float2(v[2], v[3]);
            if (bi != bj) {
                dst[cbase + (size_t)c * NB + r]           = v[0];
                dst[cbase + (size_t)(c + 1) * NB + r]     = v[1];
                dst[cbase + (size_t)c * NB + r + 8]       = v[2];
                dst[cbase + (size_t)(c + 1) * NB + r + 8] = v[3];
            }
        }
    }
}

// ---------------- final fused epilogue: one block per (b,n) row ----------------
__global__ void final_k(float* __restrict__ out) {
    int bn = blockIdx.x;
    size_t base = (size_t)bn * NB;

    float yv[4];
    float ssy = 0.f;
    #pragma unroll
    for (int i = 0; i < 4; i++) {
        int k = threadIdx.x + i * 256;
        float y = g_Y[base + k];
        yv[i] = y;
        ssy += y * y;
    }
    float toty = blockReduce256(ssy);
    float invny = 1.0f / fmaxf(sqrtf(toty), 1e-12f);

    float tv[4];
    float sst = 0.f;
    #pragma unroll
    for (int i = 0; i < 4; i++) {
        int k = threadIdx.x + i * 256;
        float t = fabsf(0.5f * g_S[base + k] + sqrtf(yv[i] * invny)) + EPSF;
        tv[i] = t;
        sst += t * t;
    }
    float tott = blockReduce256(sst);
    float invnt = 1.0f / fmaxf(sqrtf(tott), 1e-12f);

    #pragma unroll
    for (int i = 0; i < 4; i++) {
        int k = threadIdx.x + i * 256;
        out[base + k] = g_ATT[base + k] * tv[i] * invnt;
    }
}

// ---------------- launch ----------------
extern "C" void kernel_launch(void* const* d_in, const int* in_sizes, int n_in,
                              void* d_out, int out_size) {
    const float* context = (const float*)d_in[0];
    const float* acc_u   = (const float*)d_in[1];
    const float* acc_v   = (const float*)d_in[2];
    const float* uv      = (const float*)d_in[3];
    const float* uva     = (const float*)d_in[4];
    const float* speed   = (const float*)d_in[5];
    /* d_in[6] = isPhy (unused by the reference) */
    const float* dist    = (const float*)d_in[7];
    const float* angle   = (const float*)d_in[8];
    const float* weight  = (const float*)d_in[9];
    float* out = (float*)d_out;

    prep_small_k<<<(BB * NB + 255) / 256, 256>>>(acc_u, acc_v, uv, uva, speed);
    angle_k<<<(NB * NB + 255) / 256, 256>>>(angle);
    buildA_k<<<BB * NB, 128>>>(context, weight);
    selfwind_k<<<BB * NB, 256>>>(dist);

    dim3 gg(36, BB);                        // 8 tiles -> 36 lower-triangular tile pairs
    syrk_mma_k<<<gg, 256>>>(0);             // attention = relu(A A^T)
    syrk_mma_k<<<gg, 256>>>(1);             // y = gamma*(S S^T)/20 + EPS

    final_k<<<BB * NB, 256>>>(out);
}

// round 14
// speedup vs baseline: 1.8574x; 1.0765x over previous
#include <cuda_runtime.h>
#include <cuda_bf16.h>
#include <math.h>
#include <stdint.h>

#define EPSF 1e-05f
#define NB 1024
#define BB 8
#define DD 128
#define PP 16
#define KA (PP*DD)   /* 2048 */

// ---------------- scratch (static device globals; no allocation) ----------------
__device__ __nv_bfloat16 g_Ah[(size_t)BB*NB*KA];  // 32 MiB  hi part of normalized features
__device__ __nv_bfloat16 g_Al[(size_t)BB*NB*KA];  // 32 MiB  lo part
__device__ __nv_bfloat16 g_Sh[(size_t)BB*NB*NB];  // 16 MiB  hi part of selfwind
__device__ __nv_bfloat16 g_Sl[(size_t)BB*NB*NB];  // 16 MiB  lo part
__device__ float g_S  [(size_t)BB*NB*NB];   // 32 MiB  selfwind fp32 (final epilogue)
__device__ float g_ATT[(size_t)BB*NB*NB];   // 32 MiB  relu(attention)
__device__ float g_Y  [(size_t)BB*NB*NB];   // 32 MiB  gamma*SS^T/20 + EPS
__device__ float g_cosA[(size_t)NB*NB];     // 4 MiB
__device__ float g_sinA[(size_t)NB*NB];     // 4 MiB
__device__ float g_cu[BB*NB], g_su[BB*NB], g_ta[BB*NB], g_aspd[BB*NB];

// ---------------- helpers ----------------
__device__ __forceinline__ float blockReduce256(float v) {
    __shared__ float sh[8];
    int lane = threadIdx.x & 31, w = threadIdx.x >> 5;
    #pragma unroll
    for (int o = 16; o; o >>= 1) v += __shfl_xor_sync(0xffffffffu, v, o);
    if (lane == 0) sh[w] = v;
    __syncthreads();
    float t = 0.f;
    #pragma unroll
    for (int i = 0; i < 8; i++) t += sh[i];
    __syncthreads();
    return t;
}
__device__ __forceinline__ void split_bf16(float x, __nv_bfloat16& h, __nv_bfloat16& l) {
    h = __float2bfloat16(x);
    l = __float2bfloat16(x - __bfloat162float(h));
}
__device__ __forceinline__ uint32_t smem_u32(const void* p) {
    uint32_t a;
    asm("{ .reg .u64 t; cvta.to.shared.u64 t, %1; cvt.u32.u64 %0, t; }" : "=r"(a) : "l"(p));
    return a;
}
// m16n8k16 row.col bf16 MMA with fp32 accumulate (sm_80+ PTX, no 'a' features)
__device__ __forceinline__ void mma16816(float* d, const uint32_t* a, const uint32_t* b) {
    asm volatile(
        "mma.sync.aligned.m16n8k16.row.col.f32.bf16.bf16.f32 "
        "{%0,%1,%2,%3}, {%4,%5,%6,%7}, {%8,%9}, {%0,%1,%2,%3};"
        : "+f"(d[0]), "+f"(d[1]), "+f"(d[2]), "+f"(d[3])
        : "r"(a[0]), "r"(a[1]), "r"(a[2]), "r"(a[3]), "r"(b[0]), "r"(b[1]));
}
// ldmatrix (sm_75+ PTX, no 'a' features)
__device__ __forceinline__ void ldsm_x4(uint32_t* r, uint32_t addr) {
    asm volatile("ldmatrix.sync.aligned.m8n8.x4.shared.b16 {%0,%1,%2,%3}, [%4];"
        : "=r"(r[0]), "=r"(r[1]), "=r"(r[2]), "=r"(r[3]) : "r"(addr));
}
__device__ __forceinline__ void ldsm_x2(uint32_t* r, uint32_t addr) {
    asm volatile("ldmatrix.sync.aligned.m8n8.x2.shared.b16 {%0,%1}, [%2];"
        : "=r"(r[0]), "=r"(r[1]) : "r"(addr));
}

// ---------------- small prep: per (b,n) scalars ----------------
__global__ void prep_small_k(const float* __restrict__ acc_u, const float* __restrict__ acc_v,
                             const float* __restrict__ uv,    const float* __restrict__ uva,
                             const float* __restrict__ speed) {
    int i = blockIdx.x * 256 + threadIdx.x;
    if (i >= BB * NB) return;
    float au = acc_u[i], av = acc_v[i];
    float x1 = sqrtf(au * au + av * av + EPSF);
    float x2 = fabsf(cosf(uva[i] - uv[i]));
    g_ta[i]   = x1 * x2;
    float s, c;
    sincosf(uv[i], &s, &c);
    g_cu[i]   = c;
    g_su[i]   = s;
    g_aspd[i] = fabsf(speed[i]);
}

// ---------------- sincos of angle (N x N) ----------------
__global__ void angle_k(const float* __restrict__ angle) {
    int i = blockIdx.x * 256 + threadIdx.x;
    if (i >= NB * NB) return;
    float s, c;
    sincosf(angle[i], &s, &c);
    g_cosA[i] = c;
    g_sinA[i] = s;
}

// ---------------- build A (bf16 hi/lo): one block per (b,n), 128 threads (d) ----------------
__global__ void buildA_k(const float* __restrict__ context, const float* __restrict__ weight) {
    int bn = blockIdx.x;
    int d  = threadIdx.x;
    float c = context[(size_t)bn * DD + d];
    __shared__ float red[PP][4];
    float vp[PP];
    int lane = d & 31, w = d >> 5;
    #pragma unroll
    for (int p = 0; p < PP; p++) {
        float v = c * weight[p * DD + d];
        vp[p] = v;
        float s = v * v;
        #pragma unroll
        for (int o = 16; o; o >>= 1) s += __shfl_xor_sync(0xffffffffu, s, o);
        if (lane == 0) red[p][w] = s;
    }
    __syncthreads();
    const float invsqrtP = 0.25f;  // 1/sqrt(16): folds the /P of attention into A·A^T
    size_t base = (size_t)bn * KA + d;
    #pragma unroll
    for (int p = 0; p < PP; p++) {
        float tot = red[p][0] + red[p][1] + red[p][2] + red[p][3];
        float inv = invsqrtP / fmaxf(sqrtf(tot), 1e-12f);
        float y = vp[p] * inv;
        __nv_bfloat16 h, l;
        split_bf16(y, h, l);
        g_Ah[base + p * DD] = h;
        g_Al[base + p * DD] = l;
    }
}

// ---------------- selfwind: one block per (b,n), 256 threads ----------------
__global__ void selfwind_k(const float* __restrict__ dist) {
    int bn = blockIdx.x;
    int n  = bn & (NB - 1);
    float cu = g_cu[bn], su = g_su[bn], ta = g_ta[bn], spd = g_aspd[bn];
    float vr[4];
    float ss = 0.f;
    #pragma unroll
    for (int i = 0; i < 4; i++) {
        int k = threadIdx.x + i * 256;
        float cv = g_cosA[(size_t)n * NB + k] * cu + g_sinA[(size_t)n * NB + k] * su;
        if (k == n) cv += 0.5f * ta;                 // sigma * temp_acc on diagonal
        float v = spd * fabsf(cv) / (dist[(size_t)n * NB + k] + EPSF);
        vr[i] = v;
        ss += v * v;
    }
    float tot = blockReduce256(ss);
    float inv = 1.0f / fmaxf(sqrtf(tot), 1e-12f);
    size_t base = (size_t)bn * NB;
    #pragma unroll
    for (int i = 0; i < 4; i++) {
        int k = threadIdx.x + i * 256;
        float v = vr[i] * inv;
        g_S[base + k] = v;
        __nv_bfloat16 h, l;
        split_bf16(v, h, l);
        g_Sh[base + k] = h;
        g_Sl[base + k] = l;
    }
}

// ---------------- mma.sync batched SYRK (3-term bf16 split), triangular tiles ----------------
// mode==0: g_ATT = relu(A A^T)        K=2048
// mode==1: g_Y   = 0.07*(S S^T)+EPS   K=1024
// CTA tile 128x128, 8 warps in 2(m) x 4(n), warp tile 64x32, BK=32.
// smem rows padded: 32 bf16 data + 8 pad = 40 bf16 = 20 b32 per row.
// ldmatrix fragment loads: x4 per A m16k16 tile, x2 per B n8k16 tile (3x fewer LDS instrs).
#define BK 32
#define LDS_STRIDE 20            /* b32 per smem row */
#define TILE_B32 (128*LDS_STRIDE)

__global__ void __launch_bounds__(256, 1) syrk_mma_k(int mode) {
    __shared__ uint32_t sAh[TILE_B32], sAl[TILE_B32], sBh[TILE_B32], sBl[TILE_B32];
    const __nv_bfloat16* __restrict__ hi = mode ? g_Sh : g_Ah;
    const __nv_bfloat16* __restrict__ lo = mode ? g_Sl : g_Al;
    float* __restrict__ dst = mode ? g_Y : g_ATT;
    const int K = mode ? NB : KA;

    const int b = blockIdx.y;
    int lin = blockIdx.x;
    int bi = 0;
    while ((bi + 1) * (bi + 2) / 2 <= lin) bi++;
    int bj = lin - bi * (bi + 1) / 2;
    const int row0 = bi * 128, col0 = bj * 128;

    const int tid = threadIdx.x, wid = tid >> 5, lane = tid & 31;
    const int wm = wid >> 2, wn = wid & 3;      // warp grid 2x4
    const int g = lane >> 2, q = lane & 3;      // fragment row-group / quad

    const size_t baseA = ((size_t)b * NB + row0) * K;
    const size_t baseB = ((size_t)b * NB + col0) * K;

    const uint32_t uAh = smem_u32(sAh), uAl = smem_u32(sAl);
    const uint32_t uBh = smem_u32(sBh), uBl = smem_u32(sBl);

    // ldmatrix lane address components (b32 units within tile)
    const int aLaneRow = lane & 15;            // rows 0..15 of the m16 tile
    const int aKoff    = (lane >> 4) * 4;      // k-block 0/1 -> +16 bytes
    const int bLaneRow = lane & 7;             // rows 0..7 of the n8 tile
    const int bKoff    = ((lane >> 3) & 1) * 4;

    // precompute per-mt / per-nt row offsets (b32)
    int aRow[4], bRow[4];
    #pragma unroll
    for (int mt = 0; mt < 4; mt++) aRow[mt] = (wm * 64 + mt * 16 + aLaneRow) * LDS_STRIDE + aKoff;
    #pragma unroll
    for (int nt = 0; nt < 4; nt++) bRow[nt] = (wn * 32 + nt * 8 + bLaneRow) * LDS_STRIDE + bKoff;

    float acc[4][4][4];
    #pragma unroll
    for (int i = 0; i < 4; i++)
        #pragma unroll
        for (int j = 0; j < 4; j++)
            #pragma unroll
            for (int t = 0; t < 4; t++) acc[i][j][t] = 0.f;

    // global-load bookkeeping: 1024 uint2 per array per chunk, 4 per thread
    int ldrow[4], ldu[4];
    #pragma unroll
    for (int i = 0; i < 4; i++) { int idx = i * 256 + tid; ldrow[i] = idx >> 3; ldu[i] = idx & 7; }

    uint2 pAh[4], pAl[4], pBh[4], pBl[4];

    const int nch = K / BK;
    // prologue load chunk 0
    #pragma unroll
    for (int i = 0; i < 4; i++) {
        size_t oA = baseA + (size_t)ldrow[i] * K + ldu[i] * 4;
        size_t oB = baseB + (size_t)ldrow[i] * K + ldu[i] * 4;
        pAh[i] = *(const uint2*)(hi + oA);  pAl[i] = *(const uint2*)(lo + oA);
        pBh[i] = *(const uint2*)(hi + oB);  pBl[i] = *(const uint2*)(lo + oB);
    }
    #pragma unroll
    for (int i = 0; i < 4; i++) {
        int so = ldrow[i] * LDS_STRIDE + ldu[i] * 2;
        *(uint2*)&sAh[so] = pAh[i];  *(uint2*)&sAl[so] = pAl[i];
        *(uint2*)&sBh[so] = pBh[i];  *(uint2*)&sBl[so] = pBl[i];
    }
    __syncthreads();

    for (int ck = 0; ck < nch; ck++) {
        // prefetch next chunk into registers (overlaps with MMA below)
        if (ck + 1 < nch) {
            const int kb = (ck + 1) * BK;
            #pragma unroll
            for (int i = 0; i < 4; i++) {
                size_t oA = baseA + (size_t)ldrow[i] * K + kb + ldu[i] * 4;
                size_t oB = baseB + (size_t)ldrow[i] * K + kb + ldu[i] * 4;
                pAh[i] = *(const uint2*)(hi + oA);  pAl[i] = *(const uint2*)(lo + oA);
                pBh[i] = *(const uint2*)(hi + oB);  pBl[i] = *(const uint2*)(lo + oB);
            }
        }
        // compute: two k16 steps per chunk
        #pragma unroll
        for (int ks = 0; ks < 2; ks++) {
            const int kb32 = ks * 8;   // 16 bf16 = 8 b32
            uint32_t ah[4][4], al[4][4], bh[4][2], bl[4][2];
            #pragma unroll
            for (int mt = 0; mt < 4; mt++) {
                uint32_t ao = (uint32_t)(aRow[mt] + kb32) * 4u;
                ldsm_x4(ah[mt], uAh + ao);
                ldsm_x4(al[mt], uAl + ao);
            }
            #pragma unroll
            for (int nt = 0; nt < 4; nt++) {
                uint32_t bo = (uint32_t)(bRow[nt] + kb32) * 4u;
                ldsm_x2(bh[nt], uBh + bo);
                ldsm_x2(bl[nt], uBl + bo);
            }
            #pragma unroll
            for (int mt = 0; mt < 4; mt++)
                #pragma unroll
                for (int nt = 0; nt < 4; nt++) {
                    mma16816(acc[mt][nt], ah[mt], bh[nt]);
                    mma16816(acc[mt][nt], ah[mt], bl[nt]);
                    mma16816(acc[mt][nt], al[mt], bh[nt]);
                }
        }
        __syncthreads();
        if (ck + 1 < nch) {
            #pragma unroll
            for (int i = 0; i < 4; i++) {
                int so = ldrow[i] * LDS_STRIDE + ldu[i] * 2;
                *(uint2*)&sAh[so] = pAh[i];  *(uint2*)&sAl[so] = pAl[i];
                *(uint2*)&sBh[so] = pBh[i];  *(uint2*)&sBl[so] = pBl[i];
            }
            __syncthreads();
        }
    }

    // epilogue: pointwise + store (+ mirror for off-diagonal tiles)
    const float gscale = 1.4f / 20.0f;
    const size_t cbase = (size_t)b * NB * NB;
    #pragma unroll
    for (int mt = 0; mt < 4; mt++) {
        #pragma unroll
        for (int nt = 0; nt < 4; nt++) {
            int r = row0 + wm * 64 + mt * 16 + g;
            int c = col0 + wn * 32 + nt * 8 + q * 2;
            float v[4];
            #pragma unroll
            for (int t = 0; t < 4; t++) {
                float f = acc[mt][nt][t];
                v[t] = mode ? fmaf(f, gscale, EPSF) : fmaxf(f, 0.f);
            }
            *(float2*)&dst[cbase + (size_t)r * NB + c]       = make_float2(v[0], v[1]);
            *(float2*)&dst[cbase + (size_t)(r + 8) * NB + c] = make_float2(v[2], v[3]);
            if (bi != bj) {
                dst[cbase + (size_t)c * NB + r]           = v[0];
                dst[cbase + (size_t)(c + 1) * NB + r]     = v[1];
                dst[cbase + (size_t)c * NB + r + 8]       = v[2];
                dst[cbase + (size_t)(c + 1) * NB + r + 8] = v[3];
            }
        }
    }
}

// ---------------- final fused epilogue: one block per (b,n) row ----------------
__global__ void final_k(float* __restrict__ out) {
    int bn = blockIdx.x;
    size_t base = (size_t)bn * NB;

    float yv[4];
    float ssy = 0.f;
    #pragma unroll
    for (int i = 0; i < 4; i++) {
        int k = threadIdx.x + i * 256;
        float y = g_Y[base + k];
        yv[i] = y;
        ssy += y * y;
    }
    float toty = blockReduce256(ssy);
    float invny = 1.0f / fmaxf(sqrtf(toty), 1e-12f);

    float tv[4];
    float sst = 0.f;
    #pragma unroll
    for (int i = 0; i < 4; i++) {
        int k = threadIdx.x + i * 256;
        float t = fabsf(0.5f * g_S[base + k] + sqrtf(yv[i] * invny)) + EPSF;
        tv[i] = t;
        sst += t * t;
    }
    float tott = blockReduce256(sst);
    float invnt = 1.0f / fmaxf(sqrtf(tott), 1e-12f);

    #pragma unroll
    for (int i = 0; i < 4; i++) {
        int k = threadIdx.x + i * 256;
        out[base + k] = g_ATT[base + k] * tv[i] * invnt;
    }
}

// ---------------- launch ----------------
extern "C" void kernel_launch(void* const* d_in, const int* in_sizes, int n_in,
                              void* d_out, int out_size) {
    const float* context = (const float*)d_in[0];
    const float* acc_u   = (const float*)d_in[1];
    const float* acc_v   = (const float*)d_in[2];
    const float* uv      = (const float*)d_in[3];
    const float* uva     = (const float*)d_in[4];
    const float* speed   = (const float*)d_in[5];
    /* d_in[6] = isPhy (unused by the reference) */
    const float* dist    = (const float*)d_in[7];
    const float* angle   = (const float*)d_in[8];
    const float* weight  = (const float*)d_in[9];
    float* out = (float*)d_out;

    prep_small_k<<<(BB * NB + 255) / 256, 256>>>(acc_u, acc_v, uv, uva, speed);
    angle_k<<<(NB * NB + 255) / 256, 256>>>(angle);
    buildA_k<<<BB * NB, 128>>>(context, weight);
    selfwind_k<<<BB * NB, 256>>>(dist);

    dim3 gg(36, BB);                        // 8 tiles -> 36 lower-triangular tile pairs
    syrk_mma_k<<<gg, 256>>>(0);             // attention = relu(A A^T)
    syrk_mma_k<<<gg, 256>>>(1);             // y = gamma*(S S^T)/20 + EPS

    final_k<<<BB * NB, 256>>>(out);
}